// round 1
// baseline (speedup 1.0000x reference)
#include <cuda_runtime.h>

#define NPOS 900
#define BATCH 4
#define VV 16
#define HH 8
#define DQ 256

// One block per (b, n) row. Fully fused:
//  phase A: load query row, centers, proj weights to smem
//  phase B: votes GEMM (32 dots of length 256) -> vote_pos, per-v sigma consts
//  phase C: imap[m] = sum_v exp(-clamp(d2)/2sigma_v^2), row sum
//  phase D: x = 1 - imap/rowsum; 8x sincos; 8-head projection + relu; store
__global__ __launch_bounds__(256, 8)
void hough_fused_kernel(
    const float* __restrict__ q,       // (B,N,256)
    const float* __restrict__ ref,     // (B,N,4)
    const float* __restrict__ vote_w,  // (32,256)
    const float* __restrict__ vote_b,  // (32)
    const float* __restrict__ proj_w,  // (8,16)
    const float* __restrict__ proj_b,  // (8)
    float* __restrict__ out)           // (B,8,N,N)
{
    __shared__ float  s_q[DQ];
    __shared__ float4 s_vc[VV];        // {vfx, vfy, |vf|^2, -1/(2 sigma^2)}
    __shared__ float2 s_cen[NPOS];
    __shared__ float  s_imap[NPOS];
    __shared__ float2 s_w[HH][8];      // (w_sin, w_cos) per (h,k)
    __shared__ float  s_pb[HH];
    __shared__ float  s_red[8];
    __shared__ float  s_vp[32];

    const int blk  = blockIdx.x;
    const int b    = blk / NPOS;
    const int n    = blk % NPOS;
    const int tid  = threadIdx.x;
    const int lane = tid & 31;
    const int w    = tid >> 5;

    // ---------------- phase A: loads ----------------
    s_q[tid] = q[(b * NPOS + n) * DQ + tid];
    for (int m = tid; m < NPOS; m += 256) {
        // ref row is 16B aligned; first two floats are the center
        const float2* rp = reinterpret_cast<const float2*>(ref + (b * NPOS + m) * 4);
        s_cen[m] = rp[0];
    }
    if (tid < 64) {
        int h = tid >> 3, k = tid & 7;
        s_w[h][k] = make_float2(proj_w[h * 16 + 2 * k], proj_w[h * 16 + 2 * k + 1]);
    }
    if (tid < HH) s_pb[tid] = proj_b[tid];
    __syncthreads();

    // ---------------- phase B: votes (32 x 256 dot) ----------------
    {
        const int j0 = w * 4;
        float a0 = 0.f, a1 = 0.f, a2 = 0.f, a3 = 0.f;
        #pragma unroll
        for (int t = 0; t < 8; ++t) {
            int d = lane + t * 32;
            float qv = s_q[d];
            a0 = fmaf(qv, vote_w[(j0 + 0) * DQ + d], a0);
            a1 = fmaf(qv, vote_w[(j0 + 1) * DQ + d], a1);
            a2 = fmaf(qv, vote_w[(j0 + 2) * DQ + d], a2);
            a3 = fmaf(qv, vote_w[(j0 + 3) * DQ + d], a3);
        }
        #pragma unroll
        for (int o = 16; o > 0; o >>= 1) {
            a0 += __shfl_xor_sync(0xffffffffu, a0, o);
            a1 += __shfl_xor_sync(0xffffffffu, a1, o);
            a2 += __shfl_xor_sync(0xffffffffu, a2, o);
            a3 += __shfl_xor_sync(0xffffffffu, a3, o);
        }
        if (lane == 0) {
            s_vp[j0 + 0] = a0 + vote_b[j0 + 0];
            s_vp[j0 + 1] = a1 + vote_b[j0 + 1];
            s_vp[j0 + 2] = a2 + vote_b[j0 + 2];
            s_vp[j0 + 3] = a3 + vote_b[j0 + 3];
        }
    }
    __syncthreads();

    if (tid < VV) {
        int v = tid;
        float rx = ref[(b * NPOS + n) * 4 + 0];
        float ry = ref[(b * NPOS + n) * 4 + 1];
        float vfx = rx + s_vp[2 * v + 0];
        float vfy = ry + s_vp[2 * v + 1];
        // reference quirk: sigma_flat = tile(sigma,(1,V,1)) -> index (n*V+v) mod N
        int idx = (n * VV + v) % NPOS;
        float r2 = ref[(b * NPOS + idx) * 4 + 2];
        float r3 = ref[(b * NPOS + idx) * 4 + 3];
        float sigma = (r2 + r3) * 0.25f;
        float den = fmaxf(2.0f * sigma * sigma, 1e-38f);
        float ninv = -1.0f / den;
        s_vc[v] = make_float4(vfx, vfy, fmaf(vfx, vfx, vfy * vfy), ninv);
    }
    __syncthreads();

    // ---------------- phase C: imap row + row sum ----------------
    float rowsum = 0.f;
    for (int m = tid; m < NPOS; m += 256) {
        float2 c = s_cen[m];
        float cm2 = fmaf(c.x, c.x, c.y * c.y);
        float acc = 0.f;
        #pragma unroll
        for (int v = 0; v < VV; ++v) {
            float4 p = s_vc[v];
            float dot = fmaf(p.x, c.x, p.y * c.y);
            float d2 = fmaf(-2.0f, dot, p.z + cm2);   // |vf|^2+|c|^2-2 vf.c (same as ref)
            d2 = fmaxf(d2, 0.0f);
            acc += __expf(p.w * d2);
        }
        s_imap[m] = acc;
        rowsum += acc;
    }
    #pragma unroll
    for (int o = 16; o > 0; o >>= 1)
        rowsum += __shfl_xor_sync(0xffffffffu, rowsum, o);
    if (lane == 0) s_red[w] = rowsum;
    __syncthreads();

    float total = s_red[0];
    #pragma unroll
    for (int i = 1; i < 8; ++i) total += s_red[i];
    const float invd = 1.0f / fmaxf(total, 1e-12f);

    // omega_k = 100 / 10000^(k/8) = 100 * 10^(-k/2)
    const float omega[8] = {100.0f, 31.622776601683793f, 10.0f, 3.1622776601683795f,
                            1.0f, 0.31622776601683794f, 0.1f, 0.031622776601683794f};

    // ---------------- phase D: pos-embed + projection + relu ----------------
    for (int m = tid; m < NPOS; m += 256) {
        float x = 1.0f - s_imap[m] * invd;
        float sv[8], cv[8];
        #pragma unroll
        for (int k = 0; k < 8; ++k) {
            float a = x * omega[k];
            __sincosf(a, &sv[k], &cv[k]);
        }
        #pragma unroll
        for (int h = 0; h < HH; ++h) {
            float acc = s_pb[h];
            #pragma unroll
            for (int k = 0; k < 8; ++k) {
                float2 wk = s_w[h][k];
                acc = fmaf(wk.x, sv[k], fmaf(wk.y, cv[k], acc));
            }
            out[((b * HH + h) * NPOS + n) * NPOS + m] = fmaxf(acc, 0.0f);
        }
    }
}

extern "C" void kernel_launch(void* const* d_in, const int* in_sizes, int n_in,
                              void* d_out, int out_size) {
    // metadata order: queries, current_ref_points, prev_ref_points (unused),
    //                 vote_w, vote_b, proj_w, proj_b
    const float* q      = (const float*)d_in[0];
    const float* ref    = (const float*)d_in[1];
    const float* vote_w = (const float*)d_in[3];
    const float* vote_b = (const float*)d_in[4];
    const float* proj_w = (const float*)d_in[5];
    const float* proj_b = (const float*)d_in[6];
    float* out = (float*)d_out;

    (void)in_sizes; (void)n_in; (void)out_size;

    dim3 grid(BATCH * NPOS);
    dim3 block(256);
    hough_fused_kernel<<<grid, block>>>(q, ref, vote_w, vote_b, proj_w, proj_b, out);
}

// round 2
// speedup vs baseline: 1.9322x; 1.9322x over previous
#include <cuda_runtime.h>

#define NPOS 900
#define BATCH 4
#define VV 16
#define HH 8
#define DQ 256

__device__ __forceinline__ unsigned long long pk2(float lo, float hi) {
    unsigned long long r;
    asm("mov.b64 %0,{%1,%2};" : "=l"(r) : "f"(lo), "f"(hi));
    return r;
}
__device__ __forceinline__ void upk2(unsigned long long v, float& lo, float& hi) {
    asm("mov.b64 {%0,%1},%2;" : "=f"(lo), "=f"(hi) : "l"(v));
}
__device__ __forceinline__ unsigned long long ffma2(unsigned long long a,
                                                    unsigned long long b,
                                                    unsigned long long c) {
    unsigned long long r;
    asm("fma.rn.f32x2 %0,%1,%2,%3;" : "=l"(r) : "l"(a), "l"(b), "l"(c));
    return r;
}

// One block per (b, n) row. Fully fused; output rows staged in smem and
// drained as 8 contiguous 3.6KB float4 bursts (one per head) to fix DRAM
// write-stream thrash.
__global__ __launch_bounds__(256, 5)
void hough_fused_kernel(
    const float* __restrict__ q,       // (B,N,256)
    const float* __restrict__ ref,     // (B,N,4)
    const float* __restrict__ vote_w,  // (32,256)
    const float* __restrict__ vote_b,  // (32)
    const float* __restrict__ proj_w,  // (8,16)
    const float* __restrict__ proj_b,  // (8)
    float* __restrict__ out)           // (B,8,N,N)
{
    __shared__ float  s_q[DQ];
    __shared__ float4 s_vc[VV];                 // {vfx, vfy, |vf|^2, -1/(2 sigma^2)}
    __shared__ float2 s_cen[NPOS];
    __shared__ float  s_imap[NPOS];
    __shared__ float  s_out[HH][NPOS];          // staged output rows (28.8 KB)
    __shared__ unsigned long long s_w2[HH][8];  // packed (w_sin, w_cos)
    __shared__ float  s_pb[HH];
    __shared__ float  s_red[8];
    __shared__ float  s_vp[32];

    const int blk  = blockIdx.x;
    const int b    = blk / NPOS;
    const int n    = blk % NPOS;
    const int tid  = threadIdx.x;
    const int lane = tid & 31;
    const int w    = tid >> 5;

    // ---------------- phase A: loads ----------------
    s_q[tid] = q[(b * NPOS + n) * DQ + tid];
    for (int m = tid; m < NPOS; m += 256) {
        const float2* rp = reinterpret_cast<const float2*>(ref + (b * NPOS + m) * 4);
        s_cen[m] = rp[0];
    }
    if (tid < 64) {
        int h = tid >> 3, k = tid & 7;
        s_w2[h][k] = pk2(proj_w[h * 16 + 2 * k], proj_w[h * 16 + 2 * k + 1]);
    }
    if (tid < HH) s_pb[tid] = proj_b[tid];
    __syncthreads();

    // ---------------- phase B: votes (32 x 256 dot) ----------------
    {
        const int j0 = w * 4;
        float a0 = 0.f, a1 = 0.f, a2 = 0.f, a3 = 0.f;
        #pragma unroll
        for (int t = 0; t < 8; ++t) {
            int d = lane + t * 32;
            float qv = s_q[d];
            a0 = fmaf(qv, vote_w[(j0 + 0) * DQ + d], a0);
            a1 = fmaf(qv, vote_w[(j0 + 1) * DQ + d], a1);
            a2 = fmaf(qv, vote_w[(j0 + 2) * DQ + d], a2);
            a3 = fmaf(qv, vote_w[(j0 + 3) * DQ + d], a3);
        }
        #pragma unroll
        for (int o = 16; o > 0; o >>= 1) {
            a0 += __shfl_xor_sync(0xffffffffu, a0, o);
            a1 += __shfl_xor_sync(0xffffffffu, a1, o);
            a2 += __shfl_xor_sync(0xffffffffu, a2, o);
            a3 += __shfl_xor_sync(0xffffffffu, a3, o);
        }
        if (lane == 0) {
            s_vp[j0 + 0] = a0 + vote_b[j0 + 0];
            s_vp[j0 + 1] = a1 + vote_b[j0 + 1];
            s_vp[j0 + 2] = a2 + vote_b[j0 + 2];
            s_vp[j0 + 3] = a3 + vote_b[j0 + 3];
        }
    }
    __syncthreads();

    if (tid < VV) {
        int v = tid;
        float rx = ref[(b * NPOS + n) * 4 + 0];
        float ry = ref[(b * NPOS + n) * 4 + 1];
        float vfx = rx + s_vp[2 * v + 0];
        float vfy = ry + s_vp[2 * v + 1];
        // reference quirk: sigma_flat = tile(sigma,(1,V,1)) -> index (n*V+v) mod N
        int idx = (n * VV + v) % NPOS;
        float r2 = ref[(b * NPOS + idx) * 4 + 2];
        float r3 = ref[(b * NPOS + idx) * 4 + 3];
        float sigma = (r2 + r3) * 0.25f;
        float den = fmaxf(2.0f * sigma * sigma, 1e-38f);
        float ninv = -1.0f / den;
        s_vc[v] = make_float4(vfx, vfy, fmaf(vfx, vfx, vfy * vfy), ninv);
    }
    __syncthreads();

    // ---------------- phase C: imap row + row sum ----------------
    float rowsum = 0.f;
    for (int m = tid; m < NPOS; m += 256) {
        float2 c = s_cen[m];
        float cm2 = fmaf(c.x, c.x, c.y * c.y);
        float acc = 0.f;
        #pragma unroll
        for (int v = 0; v < VV; ++v) {
            float4 p = s_vc[v];
            float dot = fmaf(p.x, c.x, p.y * c.y);
            float d2 = fmaf(-2.0f, dot, p.z + cm2);
            d2 = fmaxf(d2, 0.0f);
            acc += __expf(p.w * d2);
        }
        s_imap[m] = acc;
        rowsum += acc;
    }
    #pragma unroll
    for (int o = 16; o > 0; o >>= 1)
        rowsum += __shfl_xor_sync(0xffffffffu, rowsum, o);
    if (lane == 0) s_red[w] = rowsum;
    __syncthreads();

    float total = s_red[0];
    #pragma unroll
    for (int i = 1; i < 8; ++i) total += s_red[i];
    const float invd = 1.0f / fmaxf(total, 1e-12f);

    // omega_k = 100 / 10000^(k/8) = 100 * 10^(-k/2)
    const float omega[8] = {100.0f, 31.622776601683793f, 10.0f, 3.1622776601683795f,
                            1.0f, 0.31622776601683794f, 0.1f, 0.031622776601683794f};

    // ---------------- phase D: pos-embed + packed projection into smem ----------------
    for (int m = tid; m < NPOS; m += 256) {
        float x = 1.0f - s_imap[m] * invd;
        unsigned long long sc[8];
        #pragma unroll
        for (int k = 0; k < 8; ++k) {
            float s, c;
            __sincosf(x * omega[k], &s, &c);
            sc[k] = pk2(s, c);
        }
        #pragma unroll
        for (int h = 0; h < HH; ++h) {
            unsigned long long acc = pk2(s_pb[h], 0.0f);
            #pragma unroll
            for (int k = 0; k < 8; ++k)
                acc = ffma2(s_w2[h][k], sc[k], acc);
            float lo, hi;
            upk2(acc, lo, hi);
            s_out[h][m] = fmaxf(lo + hi, 0.0f);
        }
    }
    __syncthreads();

    // ---------------- phase E: burst store, one contiguous 3.6KB sweep per head ----------------
    if (tid < NPOS / 4) {
        #pragma unroll
        for (int h = 0; h < HH; ++h) {
            float4 v = *reinterpret_cast<const float4*>(&s_out[h][tid * 4]);
            float4* dst = reinterpret_cast<float4*>(
                out + ((size_t)((b * HH + h) * NPOS) + n) * NPOS);
            dst[tid] = v;
        }
    }
}

extern "C" void kernel_launch(void* const* d_in, const int* in_sizes, int n_in,
                              void* d_out, int out_size) {
    const float* q      = (const float*)d_in[0];
    const float* ref    = (const float*)d_in[1];
    const float* vote_w = (const float*)d_in[3];
    const float* vote_b = (const float*)d_in[4];
    const float* proj_w = (const float*)d_in[5];
    const float* proj_b = (const float*)d_in[6];
    float* out = (float*)d_out;

    (void)in_sizes; (void)n_in; (void)out_size;

    dim3 grid(BATCH * NPOS);
    dim3 block(256);
    hough_fused_kernel<<<grid, block>>>(q, ref, vote_w, vote_b, proj_w, proj_b, out);
}

// round 5
// speedup vs baseline: 5.5664x; 2.8809x over previous
#include <cuda_runtime.h>

#define NPOS 900
#define BATCH 4
#define VV 16
#define HH 8
#define DQ 256
#define MQUAD 225   // 900 / 4 m-values per thread

__device__ __forceinline__ unsigned long long pk2(float lo, float hi) {
    unsigned long long r;
    asm("mov.b64 %0,{%1,%2};" : "=l"(r) : "f"(lo), "f"(hi));
    return r;
}
__device__ __forceinline__ void upk2(unsigned long long v, float& lo, float& hi) {
    asm("mov.b64 {%0,%1},%2;" : "=f"(lo), "=f"(hi) : "l"(v));
}
__device__ __forceinline__ unsigned long long ffma2(unsigned long long a,
                                                    unsigned long long b,
                                                    unsigned long long c) {
    unsigned long long r;
    asm("fma.rn.f32x2 %0,%1,%2,%3;" : "=l"(r) : "l"(a), "l"(b), "l"(c));
    return r;
}

// One block per (b, n) row. Each thread owns 4 consecutive m values so every
// smem load (vote consts, projection weights) is amortized 4x, imap lives in
// registers (no staging buffer), and outputs go straight out as STG.128.
__global__ __launch_bounds__(256, 4)
void hough_fused_kernel(
    const float* __restrict__ q,       // (B,N,256)
    const float* __restrict__ ref,     // (B,N,4)
    const float* __restrict__ vote_w,  // (32,256)
    const float* __restrict__ vote_b,  // (32)
    const float* __restrict__ proj_w,  // (8,16)
    const float* __restrict__ proj_b,  // (8)
    float* __restrict__ out)           // (B,8,N,N)
{
    __shared__ float  s_q[DQ];
    __shared__ float4 s_vc[VV];                  // {vfx, vfy, |vf|^2, -1/(2 sigma^2)}
    __shared__ float2 s_cen[NPOS];
    __shared__ unsigned long long s_ws[HH][8];   // (w_sin, w_sin) duplicated
    __shared__ unsigned long long s_wc[HH][8];   // (w_cos, w_cos) duplicated
    __shared__ float  s_pb[HH];
    __shared__ float  s_red[8];
    __shared__ float  s_vp[32];

    const int blk  = blockIdx.x;
    const int b    = blk / NPOS;
    const int n    = blk % NPOS;
    const int tid  = threadIdx.x;
    const int lane = tid & 31;
    const int w    = tid >> 5;

    // ---------------- phase A: loads ----------------
    s_q[tid] = q[(b * NPOS + n) * DQ + tid];
    for (int m = tid; m < NPOS; m += 256) {
        const float2* rp = reinterpret_cast<const float2*>(ref + (b * NPOS + m) * 4);
        s_cen[m] = rp[0];
    }
    if (tid < 64) {
        int h = tid >> 3, k = tid & 7;
        float wx = proj_w[h * 16 + 2 * k];
        float wy = proj_w[h * 16 + 2 * k + 1];
        s_ws[h][k] = pk2(wx, wx);
        s_wc[h][k] = pk2(wy, wy);
    }
    if (tid < HH) s_pb[tid] = proj_b[tid];
    __syncthreads();

    // ---------------- phase B: votes (32 x 256 dot) ----------------
    {
        const int j0 = w * 4;
        float a0 = 0.f, a1 = 0.f, a2 = 0.f, a3 = 0.f;
        #pragma unroll
        for (int t = 0; t < 8; ++t) {
            int d = lane + t * 32;
            float qv = s_q[d];
            a0 = fmaf(qv, vote_w[(j0 + 0) * DQ + d], a0);
            a1 = fmaf(qv, vote_w[(j0 + 1) * DQ + d], a1);
            a2 = fmaf(qv, vote_w[(j0 + 2) * DQ + d], a2);
            a3 = fmaf(qv, vote_w[(j0 + 3) * DQ + d], a3);
        }
        #pragma unroll
        for (int o = 16; o > 0; o >>= 1) {
            a0 += __shfl_xor_sync(0xffffffffu, a0, o);
            a1 += __shfl_xor_sync(0xffffffffu, a1, o);
            a2 += __shfl_xor_sync(0xffffffffu, a2, o);
            a3 += __shfl_xor_sync(0xffffffffu, a3, o);
        }
        if (lane == 0) {
            s_vp[j0 + 0] = a0 + vote_b[j0 + 0];
            s_vp[j0 + 1] = a1 + vote_b[j0 + 1];
            s_vp[j0 + 2] = a2 + vote_b[j0 + 2];
            s_vp[j0 + 3] = a3 + vote_b[j0 + 3];
        }
    }
    __syncthreads();

    if (tid < VV) {
        int v = tid;
        float rx = ref[(b * NPOS + n) * 4 + 0];
        float ry = ref[(b * NPOS + n) * 4 + 1];
        float vfx = rx + s_vp[2 * v + 0];
        float vfy = ry + s_vp[2 * v + 1];
        // reference quirk: sigma_flat = tile(sigma,(1,V,1)) -> index (n*V+v) mod N
        int idx = (n * VV + v) % NPOS;
        float r2 = ref[(b * NPOS + idx) * 4 + 2];
        float r3 = ref[(b * NPOS + idx) * 4 + 3];
        float sigma = (r2 + r3) * 0.25f;
        float den = fmaxf(2.0f * sigma * sigma, 1e-38f);
        float ninv = -1.0f / den;
        s_vc[v] = make_float4(vfx, vfy, fmaf(vfx, vfx, vfy * vfy), ninv);
    }
    __syncthreads();

    // ---------------- phase C: 4 imap values per thread + row sum ----------------
    float a0 = 0.f, a1 = 0.f, a2 = 0.f, a3 = 0.f;
    if (tid < MQUAD) {
        // s_cen[4*tid..4*tid+3] : 32B aligned, read as two float4
        const float4* cp = reinterpret_cast<const float4*>(&s_cen[4 * tid]);
        float4 cA = cp[0], cB = cp[1];
        float2 c0 = make_float2(cA.x, cA.y), c1 = make_float2(cA.z, cA.w);
        float2 c2 = make_float2(cB.x, cB.y), c3 = make_float2(cB.z, cB.w);
        float q0 = fmaf(c0.x, c0.x, c0.y * c0.y);
        float q1 = fmaf(c1.x, c1.x, c1.y * c1.y);
        float q2 = fmaf(c2.x, c2.x, c2.y * c2.y);
        float q3 = fmaf(c3.x, c3.x, c3.y * c3.y);
        #pragma unroll
        for (int v = 0; v < VV; ++v) {
            float4 p = s_vc[v];
            float d0 = fmaf(-2.0f, fmaf(p.x, c0.x, p.y * c0.y), p.z + q0);
            float d1 = fmaf(-2.0f, fmaf(p.x, c1.x, p.y * c1.y), p.z + q1);
            float d2 = fmaf(-2.0f, fmaf(p.x, c2.x, p.y * c2.y), p.z + q2);
            float d3 = fmaf(-2.0f, fmaf(p.x, c3.x, p.y * c3.y), p.z + q3);
            a0 += __expf(p.w * fmaxf(d0, 0.0f));
            a1 += __expf(p.w * fmaxf(d1, 0.0f));
            a2 += __expf(p.w * fmaxf(d2, 0.0f));
            a3 += __expf(p.w * fmaxf(d3, 0.0f));
        }
    }
    float rowsum = (a0 + a1) + (a2 + a3);
    #pragma unroll
    for (int o = 16; o > 0; o >>= 1)
        rowsum += __shfl_xor_sync(0xffffffffu, rowsum, o);
    if (lane == 0) s_red[w] = rowsum;
    __syncthreads();

    float total = s_red[0];
    #pragma unroll
    for (int i = 1; i < 8; ++i) total += s_red[i];
    const float invd = 1.0f / fmaxf(total, 1e-12f);

    if (tid >= MQUAD) return;

    const float x0 = 1.0f - a0 * invd;
    const float x1 = 1.0f - a1 * invd;
    const float x2 = 1.0f - a2 * invd;
    const float x3 = 1.0f - a3 * invd;

    // omega_k = 100 / 10000^(k/8) = 100 * 10^(-k/2)
    const float omega[8] = {100.0f, 31.622776601683793f, 10.0f, 3.1622776601683795f,
                            1.0f, 0.31622776601683794f, 0.1f, 0.031622776601683794f};

    // ---------------- phase D: pos-embed + projection for 4 m at once ----------------
    unsigned long long acc[HH][2];
    #pragma unroll
    for (int h = 0; h < HH; ++h) {
        float pb = s_pb[h];
        acc[h][0] = pk2(pb, pb);
        acc[h][1] = pk2(pb, pb);
    }
    #pragma unroll
    for (int k = 0; k < 8; ++k) {
        float sA, cA, sB, cB, sC, cC, sD, cD;
        __sincosf(x0 * omega[k], &sA, &cA);
        __sincosf(x1 * omega[k], &sB, &cB);
        __sincosf(x2 * omega[k], &sC, &cC);
        __sincosf(x3 * omega[k], &sD, &cD);
        unsigned long long s01 = pk2(sA, sB), s23 = pk2(sC, sD);
        unsigned long long c01 = pk2(cA, cB), c23 = pk2(cC, cD);
        #pragma unroll
        for (int h = 0; h < HH; ++h) {
            unsigned long long ws = s_ws[h][k];
            unsigned long long wc = s_wc[h][k];
            acc[h][0] = ffma2(ws, s01, ffma2(wc, c01, acc[h][0]));
            acc[h][1] = ffma2(ws, s23, ffma2(wc, c23, acc[h][1]));
        }
    }

    // ---------------- phase E: direct STG.128 per head ----------------
    #pragma unroll
    for (int h = 0; h < HH; ++h) {
        float o0, o1, o2, o3;
        upk2(acc[h][0], o0, o1);
        upk2(acc[h][1], o2, o3);
        float4 vv = make_float4(fmaxf(o0, 0.0f), fmaxf(o1, 0.0f),
                                fmaxf(o2, 0.0f), fmaxf(o3, 0.0f));
        float4* dst = reinterpret_cast<float4*>(
            out + ((size_t)((b * HH + h) * NPOS) + n) * NPOS);
        dst[tid] = vv;
    }
}

extern "C" void kernel_launch(void* const* d_in, const int* in_sizes, int n_in,
                              void* d_out, int out_size) {
    const float* q      = (const float*)d_in[0];
    const float* ref    = (const float*)d_in[1];
    const float* vote_w = (const float*)d_in[3];
    const float* vote_b = (const float*)d_in[4];
    const float* proj_w = (const float*)d_in[5];
    const float* proj_b = (const float*)d_in[6];
    float* out = (float*)d_out;

    (void)in_sizes; (void)n_in; (void)out_size;

    dim3 grid(BATCH * NPOS);
    dim3 block(256);
    hough_fused_kernel<<<grid, block>>>(q, ref, vote_w, vote_b, proj_w, proj_b, out);
}